// round 6
// baseline (speedup 1.0000x reference)
#include <cuda_runtime.h>
#include <cstdint>

#define B_SZ 16384
#define F_SZ 9000
#define KPAD 9024            // 282 * 32
#define NCH  282             // K chunks of 32
#define STG_SZ 16384         // per-stage smem: Ah 4K | Al 4K | Wh 4K | Wl 4K
#define AH_OFF 0
#define AL_OFF 4096
#define WH_OFF 8192
#define WL_OFF 12288
#define SMEM_DYN (3 * STG_SZ)   // 49152 B exactly; NO static smem in ft kernel

__device__ float g_scratch[B_SZ * 256];
__device__ int g_mode;
__device__ signed char g_wqh[128 * KPAD];
__device__ signed char g_wql[128 * KPAD];

__device__ __forceinline__ float screlu(float x) {
    x = fminf(fmaxf(x, 0.0f), 1.0f);
    return x * x;
}

__device__ __forceinline__ uint32_t smem_u32(const void* p) {
    uint32_t a;
    asm("{ .reg .u64 t; cvta.to.shared.u64 t, %1; cvt.u32.u64 %0, t; }" : "=r"(a) : "l"(p));
    return a;
}

// XOR swizzle: row r (32B/row), 16B-half h -> conflict-free for ldmatrix/STS
#define SWZ(r, h) ((uint32_t)((r) * 32 + (((h) ^ (((r) >> 2) & 1)) << 4)))

#define LDSM_X4(r, addr)                                                         \
    asm volatile("ldmatrix.sync.aligned.m8n8.x4.shared.b16 {%0,%1,%2,%3}, [%4];" \
                 : "=r"((r)[0]), "=r"((r)[1]), "=r"((r)[2]), "=r"((r)[3])        \
                 : "r"(addr))

#define IMMA(c, a, bb0, bb1)                                                     \
    asm volatile("mma.sync.aligned.m16n8k32.row.col.s32.u8.s8.s32 "              \
                 "{%0,%1,%2,%3}, {%4,%5,%6,%7}, {%8,%9}, {%0,%1,%2,%3};"         \
                 : "+r"((c)[0]), "+r"((c)[1]), "+r"((c)[2]), "+r"((c)[3])        \
                 : "r"((a)[0]), "r"((a)[1]), "r"((a)[2]), "r"((a)[3]),           \
                   "r"(bb0), "r"(bb1))

// 4 fp32 in [0,1) -> packed u8 hi limbs + u8 lo limbs (A = (hi*256+lo)/65535)
__device__ __forceinline__ void quantA(float4 v, uint32_t& hi, uint32_t& lo) {
    int i0 = __float2int_rn(v.x * 65535.0f);
    int i1 = __float2int_rn(v.y * 65535.0f);
    int i2 = __float2int_rn(v.z * 65535.0f);
    int i3 = __float2int_rn(v.w * 65535.0f);
    uint32_t h01 = __byte_perm(i0, i1, 0x0051);
    uint32_t h23 = __byte_perm(i2, i3, 0x0051);
    hi = __byte_perm(h01, h23, 0x5410);
    uint32_t l01 = __byte_perm(i0, i1, 0x0040);
    uint32_t l23 = __byte_perm(i2, i3, 0x0040);
    lo = __byte_perm(l01, l23, 0x5410);
}

// ---------------------------------------------------------------------------
// Kernel 0: stm dtype sniff -> g_mode (0=int32, 1=uint8 bool, 2=float32)
// ---------------------------------------------------------------------------
__global__ void stm_detect_kernel(const unsigned char* __restrict__ p) {
    __shared__ int fFloat, fBool;
    if (threadIdx.x == 0) { fFloat = 0; fBool = 0; }
    __syncthreads();
    int lf = 0, lb = 0;
    for (int i = threadIdx.x; i < B_SZ; i += blockDim.x) {
        unsigned char v = p[i];
        if (v == 0x80u || v == 0x3fu) lf = 1;
        else if (v != 0u && (i & 3) != 0) lb = 1;
    }
    if (lf) atomicOr(&fFloat, 1);
    if (lb) atomicOr(&fBool, 1);
    __syncthreads();
    if (threadIdx.x == 0) g_mode = fFloat ? 2 : (fBool ? 1 : 0);
}

// ---------------------------------------------------------------------------
// Kernel 0b: pre-quantize ft_w into two s8 limbs, zero-padded to KPAD.
// W = (wh*256 + wl) / 131072   (scale 512 then 256)
// ---------------------------------------------------------------------------
__global__ void wquant_kernel(const float* __restrict__ ftw) {
    int idx = blockIdx.x * 256 + threadIdx.x;     // < 128*KPAD
    int n = idx / KPAD, k = idx - n * KPAD;
    float w = (k < F_SZ) ? ftw[n * F_SZ + k] : 0.0f;
    float wv = w * 512.0f;
    int wh = __float2int_rn(wv);
    int wl = __float2int_rn((wv - (float)wh) * 256.0f);
    if (wl > 127) wl = 127;
    g_wqh[idx] = (signed char)wh;
    g_wql[idx] = (signed char)wl;
}

// ---------------------------------------------------------------------------
// Kernel 1: int8 IMMA feature-transform GEMM (3-limb) + bias + screlu.
// grid (B/128, 2 colors), 512 threads, 16 warps (4m x 4n, 32x32 warp tiles),
// 3-stage cp.async/LDG pipeline, 48KB dynamic smem.
// ---------------------------------------------------------------------------
__global__ __launch_bounds__(512, 1)
void ft_imma_kernel(const float* __restrict__ white,
                    const float* __restrict__ black,
                    const float* __restrict__ ftb) {
    extern __shared__ char smc[];
    const int t = threadIdx.x;
    const int lane = t & 31, wid = t >> 5;
    const int wm = wid >> 2, wn = wid & 3;
    const int color = blockIdx.y;
    const int row0 = blockIdx.x * 128;
    const float* __restrict__ A = color ? black : white;
    const uint32_t base = smem_u32(smc);

    // loader roles: t<256 -> A (convert), t>=256 -> W (cp.async)
    const bool isA = t < 256;
    const int lrow = (t & 255) >> 1;
    const int lh = t & 1;
    const float* aRow = A + (size_t)(row0 + lrow) * F_SZ;
    const uint32_t aDst = SWZ(lrow, lh);
    const signed char* whSrc = g_wqh + (size_t)lrow * KPAD + lh * 16;
    const signed char* wlSrc = g_wql + (size_t)lrow * KPAD + lh * 16;
    const uint32_t wDst = SWZ(lrow, lh);

    float4 aReg[4];

    auto loadA = [&](int ch) {
        if (!isA) return;
        const int kb = ch * 32 + lh * 16;
        if (kb + 16 <= F_SZ) {
#pragma unroll
            for (int j = 0; j < 4; j++) aReg[j] = *(const float4*)(aRow + kb + j * 4);
        } else {
#pragma unroll
            for (int j = 0; j < 4; j++) {
                float v[4];
#pragma unroll
                for (int e = 0; e < 4; e++) {
                    int k = kb + j * 4 + e;
                    v[e] = (k < F_SZ) ? aRow[k] : 0.0f;
                }
                aReg[j] = make_float4(v[0], v[1], v[2], v[3]);
            }
        }
    };
    auto cpW = [&](int ch, int stg) {
        if (isA) return;
        const uint32_t sb = base + stg * STG_SZ;
        asm volatile("cp.async.ca.shared.global [%0], [%1], 16;"
                     :: "r"(sb + WH_OFF + wDst), "l"(whSrc + ch * 32) : "memory");
        asm volatile("cp.async.ca.shared.global [%0], [%1], 16;"
                     :: "r"(sb + WL_OFF + wDst), "l"(wlSrc + ch * 32) : "memory");
    };
    auto convA = [&](int stg) {
        if (!isA) return;
        uint32_t hi[4], lo[4];
#pragma unroll
        for (int j = 0; j < 4; j++) quantA(aReg[j], hi[j], lo[j]);
        char* p = smc + stg * STG_SZ;
        *(uint4*)(p + AH_OFF + aDst) = make_uint4(hi[0], hi[1], hi[2], hi[3]);
        *(uint4*)(p + AL_OFF + aDst) = make_uint4(lo[0], lo[1], lo[2], lo[3]);
    };

    // ldmatrix per-lane offsets
    const int rA = wm * 32 + (lane & 15);
    const uint32_t offA = SWZ(rA, lane >> 4);
    const int rB = wn * 32 + ((lane >> 4) << 3) + (lane & 7);
    const uint32_t offB = SWZ(rB, (lane >> 3) & 1);

    int acc1[2][4][4], acc2[2][4][4];
#pragma unroll
    for (int mi = 0; mi < 2; mi++)
#pragma unroll
        for (int o = 0; o < 4; o++)
#pragma unroll
            for (int q = 0; q < 4; q++) { acc1[mi][o][q] = 0; acc2[mi][o][q] = 0; }

    // ---- prologue: chunks 0,1 -> stages 0,1
    loadA(0); cpW(0, 0);
    asm volatile("cp.async.commit_group;" ::: "memory");
    convA(0);
    loadA(1); cpW(1, 1);
    asm volatile("cp.async.commit_group;" ::: "memory");
    convA(1);
    asm volatile("cp.async.wait_group 0;" ::: "memory");
    __syncthreads();

    int stg = 0, stg2 = 2;   // stg = c%3, stg2 = (c+2)%3
    for (int c = 0; c < NCH; ++c) {
        if (c + 2 < NCH) { loadA(c + 2); cpW(c + 2, stg2); }
        asm volatile("cp.async.commit_group;" ::: "memory");

        // ---- MMA on stage stg
        {
            const uint32_t sb = base + stg * STG_SZ;
            uint32_t ah[2][4], bh[2][4], bl[2][4], al[2][4];
            LDSM_X4(ah[0], sb + AH_OFF + offA);
            LDSM_X4(ah[1], sb + AH_OFF + offA + 512);
            LDSM_X4(bh[0], sb + WH_OFF + offB);
            LDSM_X4(bh[1], sb + WH_OFF + offB + 512);
            // T1 = hi * wh
#pragma unroll
            for (int mi = 0; mi < 2; mi++)
#pragma unroll
                for (int p = 0; p < 2; p++) {
                    IMMA(acc1[mi][p * 2 + 0], ah[mi], bh[p][0], bh[p][1]);
                    IMMA(acc1[mi][p * 2 + 1], ah[mi], bh[p][2], bh[p][3]);
                }
            LDSM_X4(bl[0], sb + WL_OFF + offB);
            LDSM_X4(bl[1], sb + WL_OFF + offB + 512);
            // T2 += hi * wl
#pragma unroll
            for (int mi = 0; mi < 2; mi++)
#pragma unroll
                for (int p = 0; p < 2; p++) {
                    IMMA(acc2[mi][p * 2 + 0], ah[mi], bl[p][0], bl[p][1]);
                    IMMA(acc2[mi][p * 2 + 1], ah[mi], bl[p][2], bl[p][3]);
                }
            LDSM_X4(al[0], sb + AL_OFF + offA);
            LDSM_X4(al[1], sb + AL_OFF + offA + 512);
            // T2 += lo * wh
#pragma unroll
            for (int mi = 0; mi < 2; mi++)
#pragma unroll
                for (int p = 0; p < 2; p++) {
                    IMMA(acc2[mi][p * 2 + 0], al[mi], bh[p][0], bh[p][1]);
                    IMMA(acc2[mi][p * 2 + 1], al[mi], bh[p][2], bh[p][3]);
                }
        }

        if (c + 2 < NCH) convA(stg2);
        asm volatile("cp.async.wait_group 1;" ::: "memory");
        __syncthreads();

        if (++stg == 3) stg = 0;
        if (++stg2 == 3) stg2 = 0;
    }

    // ---- epilogue: combine limbs (exact in double), +bias, screlu -> scratch
    const double INV = 1.0 / (65535.0 * 131072.0);
    const int mrow = lane >> 2;
    const int mcol = (lane & 3) * 2;
#pragma unroll
    for (int mi = 0; mi < 2; mi++) {
#pragma unroll
        for (int hf = 0; hf < 2; hf++) {
            const int r = row0 + wm * 32 + mi * 16 + mrow + hf * 8;
            float* dstRow = g_scratch + (size_t)r * 256 + color * 128;
#pragma unroll
            for (int o = 0; o < 4; o++) {
                const int cidx = wn * 32 + o * 8 + mcol;
                float2 bias = *(const float2*)(ftb + cidx);
                double s0 = ((double)acc1[mi][o][hf * 2 + 0] * 65536.0 +
                             (double)acc2[mi][o][hf * 2 + 0] * 256.0) * INV;
                double s1 = ((double)acc1[mi][o][hf * 2 + 1] * 65536.0 +
                             (double)acc2[mi][o][hf * 2 + 1] * 256.0) * INV;
                float2 out;
                out.x = screlu((float)s0 + bias.x);
                out.y = screlu((float)s1 + bias.y);
                *(float2*)(dstRow + cidx) = out;
            }
        }
    }
}

// ---------------------------------------------------------------------------
// Kernel 2: tail MLP, one warp per batch row; stm decoded inline via g_mode.
// ---------------------------------------------------------------------------
__global__ __launch_bounds__(256)
void tail_kernel(const unsigned char* __restrict__ stm,
                 const float* __restrict__ l1w, const float* __restrict__ l1b,
                 const float* __restrict__ l2w, const float* __restrict__ l2b,
                 const float* __restrict__ outw, const float* __restrict__ outb,
                 float* __restrict__ out) {
    __shared__ float l1wT[256 * 32];
    __shared__ float l1b_s[32];
    __shared__ float l2wT[32 * 32];
    __shared__ float l2b_s[32];
    __shared__ float outw_s[32];
    __shared__ float xs[8][256];
    __shared__ float x1s[8][32];

    const int t = threadIdx.x;
    for (int idx = t; idx < 32 * 256; idx += 256) {
        int i = idx >> 8, k = idx & 255;
        l1wT[k * 32 + i] = l1w[idx];
    }
    for (int idx = t; idx < 32 * 32; idx += 256) {
        int i = idx >> 5, j = idx & 31;
        l2wT[j * 32 + i] = l2w[idx];
    }
    if (t < 32) {
        l1b_s[t] = l1b[t];
        l2b_s[t] = l2b[t];
        outw_s[t] = outw[t];
    }
    __syncthreads();

    const int w = t >> 5;
    const int lane = t & 31;
    const int r = blockIdx.x * 8 + w;

    const int mode = g_mode;
    bool s;
    if (mode == 2)      s = (((const float*)(const void*)stm)[r] != 0.0f);
    else if (mode == 1) s = (stm[r] != 0u);
    else                s = (((const int*)(const void*)stm)[r] != 0);
    const int rot = s ? 128 : 0;

    const float* src = g_scratch + (size_t)r * 256;
#pragma unroll
    for (int j = lane; j < 256; j += 32)
        xs[w][j] = src[(j + rot) & 255];
    __syncwarp();

    float o1 = l1b_s[lane];
#pragma unroll 8
    for (int k = 0; k < 256; k++)
        o1 += l1wT[k * 32 + lane] * xs[w][k];
    x1s[w][lane] = screlu(o1);
    __syncwarp();

    float o2 = l2b_s[lane];
#pragma unroll
    for (int j = 0; j < 32; j++)
        o2 += l2wT[j * 32 + lane] * x1s[w][j];

    float v = screlu(o2) * outw_s[lane];
#pragma unroll
    for (int off = 16; off; off >>= 1)
        v += __shfl_xor_sync(0xffffffffu, v, off);
    if (lane == 0) out[r] = v + outb[0];
}

// ---------------------------------------------------------------------------
extern "C" void kernel_launch(void* const* d_in, const int* in_sizes, int n_in,
                              void* d_out, int out_size) {
    const float* white = (const float*)d_in[0];
    const float* black = (const float*)d_in[1];
    const unsigned char* stm = (const unsigned char*)d_in[2];
    const float* ftw  = (const float*)d_in[3];
    const float* ftb  = (const float*)d_in[4];
    const float* l1w  = (const float*)d_in[5];
    const float* l1b  = (const float*)d_in[6];
    const float* l2w  = (const float*)d_in[7];
    const float* l2b  = (const float*)d_in[8];
    const float* outw = (const float*)d_in[9];
    const float* outb = (const float*)d_in[10];
    float* out = (float*)d_out;

    stm_detect_kernel<<<1, 1024>>>(stm);
    wquant_kernel<<<(128 * KPAD) / 256, 256>>>(ftw);
    ft_imma_kernel<<<dim3(B_SZ / 128, 2), 512, SMEM_DYN>>>(white, black, ftb);
    tail_kernel<<<B_SZ / 8, 256>>>(stm, l1w, l1b, l2w, l2b, outw, outb, out);
}

// round 7
// speedup vs baseline: 3.2857x; 3.2857x over previous
#include <cuda_runtime.h>
#include <cstdint>

#define B_SZ 16384
#define F_SZ 9000
#define BK   16
#define NCH  563             // ceil(9000/16); last chunk half-valid
#define PL   4096            // plane bytes: 128 rows x 32B
#define AH_OFF 0
#define AL_OFF 4096
#define WH_OFF 8192
#define WL_OFF 12288
#define STG_SZ 16384
#define SMEM_DYN (3 * STG_SZ)   // 49152 B exactly; no static smem in ft kernel

__device__ float g_scratch[B_SZ * 256];
__device__ int g_mode;
__device__ unsigned char g_wbf[NCH * 2 * PL];   // per-chunk Wh|Wl planes, smem-layout

__device__ __forceinline__ float screlu(float x) {
    x = fminf(fmaxf(x, 0.0f), 1.0f);
    return x * x;
}

__device__ __forceinline__ uint32_t smem_u32(const void* p) {
    uint32_t a;
    asm("{ .reg .u64 t; cvta.to.shared.u64 t, %1; cvt.u32.u64 %0, t; }" : "=r"(a) : "l"(p));
    return a;
}

// XOR swizzle for 32B rows: row r, 16B-half h -> conflict-free ldmatrix/STS
#define SWZ(r, h) ((uint32_t)((r) * 32 + (((h) ^ (((r) >> 2) & 1)) << 4)))

// fp32 pair -> bf16x2 hi + bf16x2 lo (3-term split)
__device__ __forceinline__ void split2(float x0, float x1, uint32_t& h, uint32_t& l) {
    asm("cvt.rn.bf16x2.f32 %0, %1, %2;" : "=r"(h) : "f"(x1), "f"(x0));
    float h0 = __uint_as_float(h << 16);
    float h1 = __uint_as_float(h & 0xffff0000u);
    float l0 = x0 - h0;
    float l1 = x1 - h1;
    asm("cvt.rn.bf16x2.f32 %0, %1, %2;" : "=r"(l) : "f"(l1), "f"(l0));
}

#define LDSM_X4(r, addr)                                                         \
    asm volatile("ldmatrix.sync.aligned.m8n8.x4.shared.b16 {%0,%1,%2,%3}, [%4];" \
                 : "=r"((r)[0]), "=r"((r)[1]), "=r"((r)[2]), "=r"((r)[3])        \
                 : "r"(addr))

#define MMA16816(c, a, bb0, bb1)                                                 \
    asm volatile("mma.sync.aligned.m16n8k16.row.col.f32.bf16.bf16.f32 "          \
                 "{%0,%1,%2,%3}, {%4,%5,%6,%7}, {%8,%9}, {%0,%1,%2,%3};"         \
                 : "+f"((c)[0]), "+f"((c)[1]), "+f"((c)[2]), "+f"((c)[3])        \
                 : "r"((a)[0]), "r"((a)[1]), "r"((a)[2]), "r"((a)[3]),           \
                   "r"(bb0), "r"(bb1))

// ---------------------------------------------------------------------------
// Kernel 0: stm dtype sniff -> g_mode (0=int32, 1=uint8 bool, 2=float32)
// ---------------------------------------------------------------------------
__global__ void stm_detect_kernel(const unsigned char* __restrict__ p) {
    __shared__ int fFloat, fBool;
    if (threadIdx.x == 0) { fFloat = 0; fBool = 0; }
    __syncthreads();
    int lf = 0, lb = 0;
    for (int i = threadIdx.x; i < B_SZ; i += blockDim.x) {
        unsigned char v = p[i];
        if (v == 0x80u || v == 0x3fu) lf = 1;
        else if (v != 0u && (i & 3) != 0) lb = 1;
    }
    if (lf) atomicOr(&fFloat, 1);
    if (lb) atomicOr(&fBool, 1);
    __syncthreads();
    if (threadIdx.x == 0) g_mode = fFloat ? 2 : (fBool ? 1 : 0);
}

// ---------------------------------------------------------------------------
// Kernel 0b: pre-convert ft_w into per-chunk bf16 hi/lo planes laid out
// exactly as the FT kernel's smem stage (SWZ layout) -> raw cp.async later.
// grid NCH blocks x 256 thr; thread t: row n = t>>1, half h = t&1.
// ---------------------------------------------------------------------------
__global__ void wprep_kernel(const float* __restrict__ ftw) {
    const int c = blockIdx.x;
    const int t = threadIdx.x;
    const int n = t >> 1, h = t & 1;
    const int kb = c * BK + h * 8;
    float4 v0 = make_float4(0, 0, 0, 0), v1 = v0;
    if (kb < F_SZ) {                     // kb+8 <= 9000 always holds when kb<9000
        const float* p = ftw + (size_t)n * F_SZ + kb;
        v0 = *(const float4*)p;
        v1 = *(const float4*)(p + 4);
    }
    uint32_t h0, l0, h1, l1, h2, l2, h3, l3;
    split2(v0.x, v0.y, h0, l0);
    split2(v0.z, v0.w, h1, l1);
    split2(v1.x, v1.y, h2, l2);
    split2(v1.z, v1.w, h3, l3);
    unsigned char* dst = g_wbf + (size_t)(c * 2) * PL + SWZ(n, h);
    *(uint4*)dst          = make_uint4(h0, h1, h2, h3);
    *(uint4*)(dst + PL)   = make_uint4(l0, l1, l2, l3);
}

// ---------------------------------------------------------------------------
// Kernel 1: bf16 3-term FT GEMM. 256 thr, warp tiles 64x32 (2m x 4n),
// 3-stage cp.async pipeline, 48KB dynamic smem, occ 2, single wave.
// ---------------------------------------------------------------------------
__global__ __launch_bounds__(256, 2)
void ft_mma_kernel(const float* __restrict__ white,
                   const float* __restrict__ black,
                   const float* __restrict__ ftb) {
    extern __shared__ char smc[];
    const int t = threadIdx.x;
    const int lane = t & 31, wid = t >> 5;
    const int wm = wid >> 2, wn = wid & 3;
    const int color = blockIdx.y;
    const int row0 = blockIdx.x * 128;
    const float* __restrict__ A = color ? black : white;
    const uint32_t base = smem_u32(smc);

    // loader mapping: thread t -> A row t>>1, k-half t&1 (8 floats)
    const int lrow = t >> 1, lh = t & 1;
    const float* aRow = A + (size_t)(row0 + lrow) * F_SZ + lh * 8;
    const uint32_t aDst = SWZ(lrow, lh);
    const unsigned char* wSrc = g_wbf + t * 16;   // linear 16B piece of plane

    float4 aReg[2];

    auto loadA = [&](int ch) {
        const int kb = ch * BK + lh * 8;
        if (kb < F_SZ) {
            aReg[0] = *(const float4*)(aRow + ch * BK);
            aReg[1] = *(const float4*)(aRow + ch * BK + 4);
        } else {
            aReg[0] = make_float4(0, 0, 0, 0);
            aReg[1] = make_float4(0, 0, 0, 0);
        }
    };
    auto cpW = [&](int ch, int stg) {
        const uint32_t sb = base + stg * STG_SZ;
        const unsigned char* s = wSrc + (size_t)(ch * 2) * PL;
        asm volatile("cp.async.cg.shared.global [%0], [%1], 16;"
                     :: "r"(sb + WH_OFF + (uint32_t)(t * 16)), "l"(s) : "memory");
        asm volatile("cp.async.cg.shared.global [%0], [%1], 16;"
                     :: "r"(sb + WL_OFF + (uint32_t)(t * 16)), "l"(s + PL) : "memory");
    };
    auto convA = [&](int stg) {
        uint32_t h0, l0, h1, l1, h2, l2, h3, l3;
        split2(aReg[0].x, aReg[0].y, h0, l0);
        split2(aReg[0].z, aReg[0].w, h1, l1);
        split2(aReg[1].x, aReg[1].y, h2, l2);
        split2(aReg[1].z, aReg[1].w, h3, l3);
        char* p = smc + stg * STG_SZ;
        *(uint4*)(p + AH_OFF + aDst) = make_uint4(h0, h1, h2, h3);
        *(uint4*)(p + AL_OFF + aDst) = make_uint4(l0, l1, l2, l3);
    };

    // ldmatrix lane offsets
    const uint32_t offA = SWZ(wm * 64 + (lane & 15), lane >> 4);
    const uint32_t offB = SWZ(wn * 32 + ((lane >> 4) << 3) + (lane & 7), (lane >> 3) & 1);

    float acc[4][4][4];
#pragma unroll
    for (int i = 0; i < 4; i++)
#pragma unroll
        for (int j = 0; j < 4; j++)
#pragma unroll
            for (int q = 0; q < 4; q++) acc[i][j][q] = 0.0f;

    // ---- prologue: chunks 0,1 -> stages 0,1
    cpW(0, 0);
    asm volatile("cp.async.commit_group;" ::: "memory");
    loadA(0); convA(0);
    cpW(1, 1);
    asm volatile("cp.async.commit_group;" ::: "memory");
    loadA(1); convA(1);
    asm volatile("cp.async.wait_group 0;" ::: "memory");
    __syncthreads();

    int stg = 0, stg2 = 2;
    for (int c = 0; c < NCH; ++c) {
        const bool more = (c + 2) < NCH;
        if (more) { loadA(c + 2); cpW(c + 2, stg2); }
        asm volatile("cp.async.commit_group;" ::: "memory");

        // ---- MMA on stage stg (3 terms: Ah*Wh, Ah*Wl, Al*Wh)
        {
            const uint32_t sb = base + stg * STG_SZ;
            uint32_t a[4][4], bh[2][4], bl[2][4];
#pragma unroll
            for (int mi = 0; mi < 4; mi++) LDSM_X4(a[mi], sb + AH_OFF + offA + mi * 512);
            LDSM_X4(bh[0], sb + WH_OFF + offB);
            LDSM_X4(bh[1], sb + WH_OFF + offB + 512);
#pragma unroll
            for (int mi = 0; mi < 4; mi++)
#pragma unroll
                for (int ni = 0; ni < 4; ni++) {
                    const int q = ni >> 1, r = (ni & 1) * 2;
                    MMA16816(acc[mi][ni], a[mi], bh[q][r], bh[q][r + 1]);
                }
            LDSM_X4(bl[0], sb + WL_OFF + offB);
            LDSM_X4(bl[1], sb + WL_OFF + offB + 512);
#pragma unroll
            for (int mi = 0; mi < 4; mi++)
#pragma unroll
                for (int ni = 0; ni < 4; ni++) {
                    const int q = ni >> 1, r = (ni & 1) * 2;
                    MMA16816(acc[mi][ni], a[mi], bl[q][r], bl[q][r + 1]);
                }
#pragma unroll
            for (int mi = 0; mi < 4; mi++) LDSM_X4(a[mi], sb + AL_OFF + offA + mi * 512);
#pragma unroll
            for (int mi = 0; mi < 4; mi++)
#pragma unroll
                for (int ni = 0; ni < 4; ni++) {
                    const int q = ni >> 1, r = (ni & 1) * 2;
                    MMA16816(acc[mi][ni], a[mi], bh[q][r], bh[q][r + 1]);
                }
        }

        if (more) convA(stg2);
        asm volatile("cp.async.wait_group 1;" ::: "memory");
        __syncthreads();

        if (++stg == 3) stg = 0;
        if (++stg2 == 3) stg2 = 0;
    }

    // ---- epilogue: +bias (gmem, L1-cached), screlu -> g_scratch
    float2 bias[4];
#pragma unroll
    for (int ni = 0; ni < 4; ni++) {
        const int n = wn * 32 + ni * 8 + (lane & 3) * 2;
        bias[ni] = *(const float2*)(ftb + n);
    }
#pragma unroll
    for (int mi = 0; mi < 4; mi++) {
#pragma unroll
        for (int hf = 0; hf < 2; hf++) {
            const int m = wm * 64 + mi * 16 + (lane >> 2) + hf * 8;
            float* dstRow = g_scratch + (size_t)(row0 + m) * 256 + color * 128;
#pragma unroll
            for (int ni = 0; ni < 4; ni++) {
                const int n = wn * 32 + ni * 8 + (lane & 3) * 2;
                float2 o;
                o.x = screlu(acc[mi][ni][hf * 2 + 0] + bias[ni].x);
                o.y = screlu(acc[mi][ni][hf * 2 + 1] + bias[ni].y);
                *(float2*)(dstRow + n) = o;
            }
        }
    }
}

// ---------------------------------------------------------------------------
// Kernel 2: tail MLP. 256 blocks x 8 warps x 8 rows/warp. Row-major padded
// l1w in smem -> LDS.128 weight + activation reads (conflict-free).
// ---------------------------------------------------------------------------
__global__ __launch_bounds__(256)
void tail_kernel(const unsigned char* __restrict__ stm,
                 const float* __restrict__ l1w, const float* __restrict__ l1b,
                 const float* __restrict__ l2w, const float* __restrict__ l2b,
                 const float* __restrict__ outw, const float* __restrict__ outb,
                 float* __restrict__ out) {
    __shared__ float l1w_s[32][260];   // padded: lane-i row reads are conflict-free
    __shared__ float xs[8][256];
    __shared__ float x1s[8][32];
    __shared__ float l2wT[32 * 32];
    __shared__ float l1b_s[32], l2b_s[32], outw_s[32];

    const int t = threadIdx.x;
    for (int idx = t; idx < 32 * 256; idx += 256) {
        int i = idx >> 8, k = idx & 255;
        l1w_s[i][k] = l1w[idx];
    }
    for (int idx = t; idx < 32 * 32; idx += 256) {
        int i = idx >> 5, j = idx & 31;
        l2wT[j * 32 + i] = l2w[idx];
    }
    if (t < 32) {
        l1b_s[t] = l1b[t];
        l2b_s[t] = l2b[t];
        outw_s[t] = outw[t];
    }
    __syncthreads();

    const int w = t >> 5;
    const int lane = t & 31;
    const int mode = g_mode;

#pragma unroll 1
    for (int rr = 0; rr < 8; ++rr) {
        const int r = blockIdx.x * 64 + w * 8 + rr;
        bool s;
        if (mode == 2)      s = (((const float*)(const void*)stm)[r] != 0.0f);
        else if (mode == 1) s = (stm[r] != 0u);
        else                s = (((const int*)(const void*)stm)[r] != 0);
        const int rot = s ? 128 : 0;

        const float* src = g_scratch + (size_t)r * 256;
#pragma unroll
        for (int p = 0; p < 2; p++) {
            const int fi = ((lane + 32 * p) * 4 + rot) & 255;
            *(float4*)&xs[w][(lane + 32 * p) * 4] = *(const float4*)(src + fi);
        }
        __syncwarp();

        float o1 = l1b_s[lane];
#pragma unroll 8
        for (int k4 = 0; k4 < 64; k4++) {
            float4 wv = *(const float4*)&l1w_s[lane][k4 * 4];
            float4 xv = *(const float4*)&xs[w][k4 * 4];
            o1 += wv.x * xv.x + wv.y * xv.y + wv.z * xv.z + wv.w * xv.w;
        }
        x1s[w][lane] = screlu(o1);
        __syncwarp();

        float o2 = l2b_s[lane];
#pragma unroll
        for (int j = 0; j < 32; j++)
            o2 += l2wT[j * 32 + lane] * x1s[w][j];

        float v = screlu(o2) * outw_s[lane];
#pragma unroll
        for (int off = 16; off; off >>= 1)
            v += __shfl_xor_sync(0xffffffffu, v, off);
        if (lane == 0) out[r] = v + outb[0];
        __syncwarp();
    }
}

// ---------------------------------------------------------------------------
extern "C" void kernel_launch(void* const* d_in, const int* in_sizes, int n_in,
                              void* d_out, int out_size) {
    const float* white = (const float*)d_in[0];
    const float* black = (const float*)d_in[1];
    const unsigned char* stm = (const unsigned char*)d_in[2];
    const float* ftw  = (const float*)d_in[3];
    const float* ftb  = (const float*)d_in[4];
    const float* l1w  = (const float*)d_in[5];
    const float* l1b  = (const float*)d_in[6];
    const float* l2w  = (const float*)d_in[7];
    const float* l2b  = (const float*)d_in[8];
    const float* outw = (const float*)d_in[9];
    const float* outb = (const float*)d_in[10];
    float* out = (float*)d_out;

    stm_detect_kernel<<<1, 1024>>>(stm);
    wprep_kernel<<<NCH, 256>>>(ftw);
    ft_mma_kernel<<<dim3(B_SZ / 128, 2), 256, SMEM_DYN>>>(white, black, ftb);
    tail_kernel<<<B_SZ / 64, 256>>>(stm, l1w, l1b, l2w, l2b, outw, outb, out);
}

// round 8
// speedup vs baseline: 3.8308x; 1.1659x over previous
#include <cuda_runtime.h>
#include <cuda_fp16.h>
#include <cstdint>

#define B_SZ 16384
#define F_SZ 9000
#define BK   16
#define NCH  563             // ceil(9000/16); last chunk half-valid
#define PL   4096            // plane bytes: 128 rows x 32B
#define A_OFF  0
#define WH_OFF 4096
#define WL_OFF 8192
#define STG_SZ 12288
#define SMEM_DYN (4 * STG_SZ)   // 49152 B exactly; no static smem in ft kernel

__device__ float g_scratch[B_SZ * 256];
__device__ int g_mode;
__device__ unsigned char g_wbf[NCH * 2 * PL];   // per-chunk Wh|Wl fp16 planes

__device__ __forceinline__ float screlu(float x) {
    x = fminf(fmaxf(x, 0.0f), 1.0f);
    return x * x;
}

__device__ __forceinline__ uint32_t smem_u32(const void* p) {
    uint32_t a;
    asm("{ .reg .u64 t; cvta.to.shared.u64 t, %1; cvt.u32.u64 %0, t; }" : "=r"(a) : "l"(p));
    return a;
}

// XOR swizzle for 32B rows: row r, 16B-half h -> conflict-free ldmatrix/STS
#define SWZ(r, h) ((uint32_t)((r) * 32 + (((h) ^ (((r) >> 2) & 1)) << 4)))

__device__ __forceinline__ uint32_t h2u(__half2 h) {
    uint32_t u;
    *(__half2*)&u = h;
    return u;
}
// fp32 pair -> fp16x2 (single limb)
__device__ __forceinline__ uint32_t cvtH2(float x0, float x1) {
    return h2u(__floats2half2_rn(x0, x1));
}
// fp32 pair -> fp16x2 hi + fp16x2 lo (2-limb W split)
__device__ __forceinline__ void splitH2(float x0, float x1, uint32_t& h, uint32_t& l) {
    __half2 hh = __floats2half2_rn(x0, x1);
    float r0 = x0 - __low2float(hh);
    float r1 = x1 - __high2float(hh);
    h = h2u(hh);
    l = h2u(__floats2half2_rn(r0, r1));
}

#define LDSM_X4(r, addr)                                                         \
    asm volatile("ldmatrix.sync.aligned.m8n8.x4.shared.b16 {%0,%1,%2,%3}, [%4];" \
                 : "=r"((r)[0]), "=r"((r)[1]), "=r"((r)[2]), "=r"((r)[3])        \
                 : "r"(addr))

#define MMA16816(c, a, bb0, bb1)                                                 \
    asm volatile("mma.sync.aligned.m16n8k16.row.col.f32.f16.f16.f32 "            \
                 "{%0,%1,%2,%3}, {%4,%5,%6,%7}, {%8,%9}, {%0,%1,%2,%3};"         \
                 : "+f"((c)[0]), "+f"((c)[1]), "+f"((c)[2]), "+f"((c)[3])        \
                 : "r"((a)[0]), "r"((a)[1]), "r"((a)[2]), "r"((a)[3]),           \
                   "r"(bb0), "r"(bb1))

// ---------------------------------------------------------------------------
// Kernel 0: stm dtype sniff -> g_mode (0=int32, 1=uint8 bool, 2=float32)
// ---------------------------------------------------------------------------
__global__ void stm_detect_kernel(const unsigned char* __restrict__ p) {
    __shared__ int fFloat, fBool;
    if (threadIdx.x == 0) { fFloat = 0; fBool = 0; }
    __syncthreads();
    int lf = 0, lb = 0;
    for (int i = threadIdx.x; i < B_SZ; i += blockDim.x) {
        unsigned char v = p[i];
        if (v == 0x80u || v == 0x3fu) lf = 1;
        else if (v != 0u && (i & 3) != 0) lb = 1;
    }
    if (lf) atomicOr(&fFloat, 1);
    if (lb) atomicOr(&fBool, 1);
    __syncthreads();
    if (threadIdx.x == 0) g_mode = fFloat ? 2 : (fBool ? 1 : 0);
}

// ---------------------------------------------------------------------------
// Kernel 0b: pre-split ft_w into per-chunk fp16 hi/lo planes (SWZ layout).
// ---------------------------------------------------------------------------
__global__ void wprep_kernel(const float* __restrict__ ftw) {
    const int c = blockIdx.x;
    const int t = threadIdx.x;
    const int n = t >> 1, h = t & 1;
    const int kb = c * BK + h * 8;
    float4 v0 = make_float4(0, 0, 0, 0), v1 = v0;
    if (kb < F_SZ) {
        const float* p = ftw + (size_t)n * F_SZ + kb;
        v0 = *(const float4*)p;
        v1 = *(const float4*)(p + 4);
    }
    uint32_t h0, l0, h1, l1, h2, l2, h3, l3;
    splitH2(v0.x, v0.y, h0, l0);
    splitH2(v0.z, v0.w, h1, l1);
    splitH2(v1.x, v1.y, h2, l2);
    splitH2(v1.z, v1.w, h3, l3);
    unsigned char* dst = g_wbf + (size_t)(c * 2) * PL + SWZ(n, h);
    *(uint4*)dst        = make_uint4(h0, h1, h2, h3);
    *(uint4*)(dst + PL) = make_uint4(l0, l1, l2, l3);
}

// ---------------------------------------------------------------------------
// Kernel 1: fp16 2-term FT GEMM (A 1-limb, W 2-limb). 256 thr, warp tiles
// 64x32 (2m x 4n), 4-stage cp.async pipeline, 48KB dyn smem, occ 2.
// ---------------------------------------------------------------------------
__global__ __launch_bounds__(256, 2)
void ft_mma_kernel(const float* __restrict__ white,
                   const float* __restrict__ black,
                   const float* __restrict__ ftb) {
    extern __shared__ char smc[];
    const int t = threadIdx.x;
    const int lane = t & 31, wid = t >> 5;
    const int wm = wid >> 2, wn = wid & 3;
    const int color = blockIdx.y;
    const int row0 = blockIdx.x * 128;
    const float* __restrict__ A = color ? black : white;
    const uint32_t base = smem_u32(smc);

    // loader mapping: thread t -> A row t>>1, k-half t&1 (8 floats)
    const int lrow = t >> 1, lh = t & 1;
    const float* aRow = A + (size_t)(row0 + lrow) * F_SZ + lh * 8;
    const uint32_t aDst = SWZ(lrow, lh);
    const unsigned char* wSrc = g_wbf + t * 16;

    float4 aReg[2];

    auto loadA = [&](int ch) {
        const int kb = ch * BK + lh * 8;
        if (kb < F_SZ) {
            aReg[0] = *(const float4*)(aRow + ch * BK);
            aReg[1] = *(const float4*)(aRow + ch * BK + 4);
        } else {
            aReg[0] = make_float4(0, 0, 0, 0);
            aReg[1] = make_float4(0, 0, 0, 0);
        }
    };
    auto cpW = [&](int ch, int stg) {
        const uint32_t sb = base + stg * STG_SZ;
        const unsigned char* s = wSrc + (size_t)(ch * 2) * PL;
        asm volatile("cp.async.cg.shared.global [%0], [%1], 16;"
                     :: "r"(sb + WH_OFF + (uint32_t)(t * 16)), "l"(s) : "memory");
        asm volatile("cp.async.cg.shared.global [%0], [%1], 16;"
                     :: "r"(sb + WL_OFF + (uint32_t)(t * 16)), "l"(s + PL) : "memory");
    };
    auto convA = [&](int stg) {
        uint4 v;
        v.x = cvtH2(aReg[0].x, aReg[0].y);
        v.y = cvtH2(aReg[0].z, aReg[0].w);
        v.z = cvtH2(aReg[1].x, aReg[1].y);
        v.w = cvtH2(aReg[1].z, aReg[1].w);
        *(uint4*)(smc + stg * STG_SZ + A_OFF + aDst) = v;
    };

    // ldmatrix lane offsets
    const uint32_t offA = SWZ(wm * 64 + (lane & 15), lane >> 4);
    const uint32_t offB = SWZ(wn * 32 + ((lane >> 4) << 3) + (lane & 7), (lane >> 3) & 1);

    float acc[4][4][4];
#pragma unroll
    for (int i = 0; i < 4; i++)
#pragma unroll
        for (int j = 0; j < 4; j++)
#pragma unroll
            for (int q = 0; q < 4; q++) acc[i][j][q] = 0.0f;

    // ---- prologue: chunks 0..2 -> stages 0..2
#pragma unroll
    for (int p = 0; p < 3; p++) {
        cpW(p, p);
        asm volatile("cp.async.commit_group;" ::: "memory");
        loadA(p);
        convA(p);
    }
    asm volatile("cp.async.wait_group 2;" ::: "memory");
    __syncthreads();

    int stg = 0, stg3 = 3;
    for (int c = 0; c < NCH; ++c) {
        const bool more = (c + 3) < NCH;
        if (more) { loadA(c + 3); cpW(c + 3, stg3); }
        asm volatile("cp.async.commit_group;" ::: "memory");

        // ---- MMA on stage stg: Ah*Wh + Ah*Wl
        {
            const uint32_t sb = base + stg * STG_SZ;
            uint32_t a[4][4], bh[2][4], bl[2][4];
#pragma unroll
            for (int mi = 0; mi < 4; mi++) LDSM_X4(a[mi], sb + A_OFF + offA + mi * 512);
            LDSM_X4(bh[0], sb + WH_OFF + offB);
            LDSM_X4(bh[1], sb + WH_OFF + offB + 512);
#pragma unroll
            for (int mi = 0; mi < 4; mi++)
#pragma unroll
                for (int ni = 0; ni < 4; ni++) {
                    const int q = ni >> 1, r = (ni & 1) * 2;
                    MMA16816(acc[mi][ni], a[mi], bh[q][r], bh[q][r + 1]);
                }
            LDSM_X4(bl[0], sb + WL_OFF + offB);
            LDSM_X4(bl[1], sb + WL_OFF + offB + 512);
#pragma unroll
            for (int mi = 0; mi < 4; mi++)
#pragma unroll
                for (int ni = 0; ni < 4; ni++) {
                    const int q = ni >> 1, r = (ni & 1) * 2;
                    MMA16816(acc[mi][ni], a[mi], bl[q][r], bl[q][r + 1]);
                }
        }

        if (more) convA(stg3);
        asm volatile("cp.async.wait_group 2;" ::: "memory");
        __syncthreads();

        stg = (stg + 1) & 3;
        stg3 = (stg3 + 1) & 3;
    }

    // ---- epilogue: +bias (gmem, L1-cached), screlu -> g_scratch
    float2 bias[4];
#pragma unroll
    for (int ni = 0; ni < 4; ni++) {
        const int n = wn * 32 + ni * 8 + (lane & 3) * 2;
        bias[ni] = *(const float2*)(ftb + n);
    }
#pragma unroll
    for (int mi = 0; mi < 4; mi++) {
#pragma unroll
        for (int hf = 0; hf < 2; hf++) {
            const int m = wm * 64 + mi * 16 + (lane >> 2) + hf * 8;
            float* dstRow = g_scratch + (size_t)(row0 + m) * 256 + color * 128;
#pragma unroll
            for (int ni = 0; ni < 4; ni++) {
                const int n = wn * 32 + ni * 8 + (lane & 3) * 2;
                float2 o;
                o.x = screlu(acc[mi][ni][hf * 2 + 0] + bias[ni].x);
                o.y = screlu(acc[mi][ni][hf * 2 + 1] + bias[ni].y);
                *(float2*)(dstRow + n) = o;
            }
        }
    }
}

// ---------------------------------------------------------------------------
// Kernel 2: tail MLP. 512 blocks x 8 warps x 4 rows/warp.
// ---------------------------------------------------------------------------
__global__ __launch_bounds__(256)
void tail_kernel(const unsigned char* __restrict__ stm,
                 const float* __restrict__ l1w, const float* __restrict__ l1b,
                 const float* __restrict__ l2w, const float* __restrict__ l2b,
                 const float* __restrict__ outw, const float* __restrict__ outb,
                 float* __restrict__ out) {
    __shared__ float l1w_s[32][260];
    __shared__ float xs[8][256];
    __shared__ float x1s[8][32];
    __shared__ float l2wT[32 * 32];
    __shared__ float l1b_s[32], l2b_s[32], outw_s[32];

    const int t = threadIdx.x;
    for (int idx = t; idx < 32 * 256; idx += 256) {
        int i = idx >> 8, k = idx & 255;
        l1w_s[i][k] = l1w[idx];
    }
    for (int idx = t; idx < 32 * 32; idx += 256) {
        int i = idx >> 5, j = idx & 31;
        l2wT[j * 32 + i] = l2w[idx];
    }
    if (t < 32) {
        l1b_s[t] = l1b[t];
        l2b_s[t] = l2b[t];
        outw_s[t] = outw[t];
    }
    __syncthreads();

    const int w = t >> 5;
    const int lane = t & 31;
    const int mode = g_mode;

#pragma unroll 1
    for (int rr = 0; rr < 4; ++rr) {
        const int r = blockIdx.x * 32 + w * 4 + rr;
        bool s;
        if (mode == 2)      s = (((const float*)(const void*)stm)[r] != 0.0f);
        else if (mode == 1) s = (stm[r] != 0u);
        else                s = (((const int*)(const void*)stm)[r] != 0);
        const int rot = s ? 128 : 0;

        const float* src = g_scratch + (size_t)r * 256;
#pragma unroll
        for (int p = 0; p < 2; p++) {
            const int fi = ((lane + 32 * p) * 4 + rot) & 255;
            *(float4*)&xs[w][(lane + 32 * p) * 4] = *(const float4*)(src + fi);
        }
        __syncwarp();

        float o1 = l1b_s[lane];
#pragma unroll 8
        for (int k4 = 0; k4 < 64; k4++) {
            float4 wv = *(const float4*)&l1w_s[lane][k4 * 4];
            float4 xv = *(const float4*)&xs[w][k4 * 4];
            o1 += wv.x * xv.x + wv.y * xv.y + wv.z * xv.z + wv.w * xv.w;
        }
        x1s[w][lane] = screlu(o1);
        __syncwarp();

        float o2 = l2b_s[lane];
#pragma unroll
        for (int j = 0; j < 32; j++)
            o2 += l2wT[j * 32 + lane] * x1s[w][j];

        float v = screlu(o2) * outw_s[lane];
#pragma unroll
        for (int off = 16; off; off >>= 1)
            v += __shfl_xor_sync(0xffffffffu, v, off);
        if (lane == 0) out[r] = v + outb[0];
        __syncwarp();
    }
}

// ---------------------------------------------------------------------------
extern "C" void kernel_launch(void* const* d_in, const int* in_sizes, int n_in,
                              void* d_out, int out_size) {
    const float* white = (const float*)d_in[0];
    const float* black = (const float*)d_in[1];
    const unsigned char* stm = (const unsigned char*)d_in[2];
    const float* ftw  = (const float*)d_in[3];
    const float* ftb  = (const float*)d_in[4];
    const float* l1w  = (const float*)d_in[5];
    const float* l1b  = (const float*)d_in[6];
    const float* l2w  = (const float*)d_in[7];
    const float* l2b  = (const float*)d_in[8];
    const float* outw = (const float*)d_in[9];
    const float* outb = (const float*)d_in[10];
    float* out = (float*)d_out;

    stm_detect_kernel<<<1, 1024>>>(stm);
    wprep_kernel<<<NCH, 256>>>(ftw);
    ft_mma_kernel<<<dim3(B_SZ / 128, 2), 256, SMEM_DYN>>>(white, black, ftb);
    tail_kernel<<<B_SZ / 32, 256>>>(stm, l1w, l1b, l2w, l2b, outw, outb, out);
}